// round 3
// baseline (speedup 1.0000x reference)
#include <cuda_runtime.h>
#include <math.h>

#define B 32
#define S 4096
#define H 1024
#define ROWS_PER_WARP 8
#define WARPS_PER_BLOCK 8
#define K1_THREADS (WARPS_PER_BLOCK * 32)                       // 256
#define ROWS_PER_BLOCK (ROWS_PER_WARP * WARPS_PER_BLOCK)        // 64
#define BLOCKS_PER_BATCH (S / ROWS_PER_BLOCK)                   // 64
#define K1_BLOCKS (B * BLOCKS_PER_BATCH)                        // 2048

// level-1 combine groups
#define CHUNKS_PER_GROUP 8
#define GROUPS_PER_BATCH (BLOCKS_PER_BATCH / CHUNKS_PER_GROUP)  // 8
#define NGROUPS (B * GROUPS_PER_BATCH)                          // 256

// Scratch (no dynamic allocation allowed)
__device__ float4 g_ctx_partial[K1_BLOCKS * (H / 4)];   // 8 MB
__device__ float  g_m_partial[K1_BLOCKS];
__device__ float4 g_ctx2[NGROUPS * (H / 4)];            // 1 MB (already /L-normalized)
__device__ float  g_M[B];
__device__ float  g_invL[B];

// ---------------------------------------------------------------------------
// Kernel 1: single streaming pass over keys + block-level combine.
// One warp = 8 rows; one block = 64 rows of one batch. grid=2048 (~6.9 waves)
// ---------------------------------------------------------------------------
__global__ __launch_bounds__(K1_THREADS)
void k1_scores_partial_ctx(const float* __restrict__ query,
                           const float* __restrict__ keys,
                           float* __restrict__ out_weights /* raw scores */)
{
    const int w    = threadIdx.x >> 5;
    const int lane = threadIdx.x & 31;
    const int blk  = blockIdx.x;
    const int b    = blk / BLOCKS_PER_BATCH;
    const int row0 = (blk % BLOCKS_PER_BATCH) * ROWS_PER_BLOCK + w * ROWS_PER_WARP;

    const float4* q4 = reinterpret_cast<const float4*>(query + (size_t)b * H);
    float4 qv[8];
#pragma unroll
    for (int j = 0; j < 8; ++j) qv[j] = q4[lane + 32 * j];

    float4 acc[8];
#pragma unroll
    for (int j = 0; j < 8; ++j) acc[j] = make_float4(0.f, 0.f, 0.f, 0.f);
    float m = -INFINITY;

    const size_t base = ((size_t)b * S + row0) * H;

#pragma unroll 2
    for (int r = 0; r < ROWS_PER_WARP; ++r) {
        const float4* k4 = reinterpret_cast<const float4*>(keys + base + (size_t)r * H);
        float4 kv[8];
#pragma unroll
        for (int j = 0; j < 8; ++j) kv[j] = k4[lane + 32 * j];

        float d = 0.f;
#pragma unroll
        for (int j = 0; j < 8; ++j) {
            d = fmaf(qv[j].x, kv[j].x, d);
            d = fmaf(qv[j].y, kv[j].y, d);
            d = fmaf(qv[j].z, kv[j].z, d);
            d = fmaf(qv[j].w, kv[j].w, d);
        }
#pragma unroll
        for (int o = 16; o > 0; o >>= 1)
            d += __shfl_xor_sync(0xFFFFFFFFu, d, o);

        if (lane == 0) out_weights[(size_t)b * S + row0 + r] = d;

        float p;
        if (d > m) {
            float scale = __expf(m - d);   // first iter: exp(-inf)=0
#pragma unroll
            for (int j = 0; j < 8; ++j) {
                acc[j].x *= scale; acc[j].y *= scale;
                acc[j].z *= scale; acc[j].w *= scale;
            }
            m = d;
            p = 1.f;
        } else {
            p = __expf(d - m);
        }
#pragma unroll
        for (int j = 0; j < 8; ++j) {
            acc[j].x = fmaf(p, kv[j].x, acc[j].x);
            acc[j].y = fmaf(p, kv[j].y, acc[j].y);
            acc[j].z = fmaf(p, kv[j].z, acc[j].z);
            acc[j].w = fmaf(p, kv[j].w, acc[j].w);
        }
    }

    // ---- block-level combine (8 warp partials -> 1 block partial) ----
    __shared__ float s_ctx[WARPS_PER_BLOCK][H];  // 32 KB
    __shared__ float s_m[WARPS_PER_BLOCK];

    if (lane == 0) s_m[w] = m;
    __syncthreads();

    float blk_m = s_m[0];
#pragma unroll
    for (int i = 1; i < WARPS_PER_BLOCK; ++i) blk_m = fmaxf(blk_m, s_m[i]);

    const float sc = __expf(m - blk_m);
    float4* srow = reinterpret_cast<float4*>(s_ctx[w]);
#pragma unroll
    for (int j = 0; j < 8; ++j) {
        float4 a = acc[j];
        a.x *= sc; a.y *= sc; a.z *= sc; a.w *= sc;
        srow[lane + 32 * j] = a;
    }
    __syncthreads();

    const int t = threadIdx.x;   // owns float4 element t of H/4=256
    float4 csum = make_float4(0.f, 0.f, 0.f, 0.f);
#pragma unroll
    for (int i = 0; i < WARPS_PER_BLOCK; ++i) {
        float4 v = reinterpret_cast<const float4*>(s_ctx[i])[t];
        csum.x += v.x; csum.y += v.y; csum.z += v.z; csum.w += v.w;
    }
    g_ctx_partial[(size_t)blk * (H / 4) + t] = csum;
    if (t == 0) g_m_partial[blk] = blk_m;
}

// ---------------------------------------------------------------------------
// Kernel 2a: per-batch global max M and inverse denominator 1/L.
// ---------------------------------------------------------------------------
#define K2_THREADS 256
#define SCORES_PER_THREAD (S / K2_THREADS)   // 16

__global__ __launch_bounds__(K2_THREADS)
void k2a_stats(const float* __restrict__ out_weights)
{
    const int b = blockIdx.x;
    const int tid = threadIdx.x;
    __shared__ float red[32];
    __shared__ float sM;

    const float* wrow = out_weights + (size_t)b * S;
    float sv[SCORES_PER_THREAD];
#pragma unroll
    for (int k = 0; k < SCORES_PER_THREAD; ++k)
        sv[k] = wrow[tid + K2_THREADS * k];

    float lm = -INFINITY;
#pragma unroll
    for (int k = 0; k < SCORES_PER_THREAD; ++k) lm = fmaxf(lm, sv[k]);
#pragma unroll
    for (int o = 16; o > 0; o >>= 1)
        lm = fmaxf(lm, __shfl_xor_sync(0xFFFFFFFFu, lm, o));
    if ((tid & 31) == 0) red[tid >> 5] = lm;
    __syncthreads();
    if (tid < 32) {
        float v = (tid < K2_THREADS / 32) ? red[tid] : -INFINITY;
#pragma unroll
        for (int o = 16; o > 0; o >>= 1)
            v = fmaxf(v, __shfl_xor_sync(0xFFFFFFFFu, v, o));
        if (tid == 0) sM = v;
    }
    __syncthreads();
    const float M = sM;

    float ls = 0.f;
#pragma unroll
    for (int k = 0; k < SCORES_PER_THREAD; ++k)
        ls += __expf(sv[k] - M);
#pragma unroll
    for (int o = 16; o > 0; o >>= 1)
        ls += __shfl_xor_sync(0xFFFFFFFFu, ls, o);
    if ((tid & 31) == 0) red[tid >> 5] = ls;
    __syncthreads();
    if (tid < 32) {
        float v = (tid < K2_THREADS / 32) ? red[tid] : 0.f;
#pragma unroll
        for (int o = 16; o > 0; o >>= 1)
            v += __shfl_xor_sync(0xFFFFFFFFu, v, o);
        if (tid == 0) { g_M[b] = M; g_invL[b] = 1.f / v; }
    }
}

// ---------------------------------------------------------------------------
// Kernel 2b: blocks 0..127 normalize weights (float4);
//            blocks 128..383 = level-1 context combine (8 chunks -> 1 group).
// ---------------------------------------------------------------------------
#define WNORM_BLOCKS ((B * S / 4) / K2_THREADS)   // 128

__global__ __launch_bounds__(K2_THREADS)
void k2b_norm_and_combine1(float* __restrict__ out_weights)
{
    if (blockIdx.x < WNORM_BLOCKS) {
        const int idx = blockIdx.x * K2_THREADS + threadIdx.x;  // float4 idx
        const int b = idx / (S / 4);
        const float M = g_M[b], invL = g_invL[b];
        float4 s = reinterpret_cast<float4*>(out_weights)[idx];
        s.x = __expf(s.x - M) * invL;
        s.y = __expf(s.y - M) * invL;
        s.z = __expf(s.z - M) * invL;
        s.w = __expf(s.w - M) * invL;
        reinterpret_cast<float4*>(out_weights)[idx] = s;
    } else {
        const int g = blockIdx.x - WNORM_BLOCKS;        // 0..255
        const int b = g / GROUPS_PER_BATCH;
        const int sub = g % GROUPS_PER_BATCH;
        const float M = g_M[b], invL = g_invL[b];
        const int t = threadIdx.x;                      // float4 element t
        float4 c = make_float4(0.f, 0.f, 0.f, 0.f);
#pragma unroll
        for (int ch = 0; ch < CHUNKS_PER_GROUP; ++ch) {
            const int pb = b * BLOCKS_PER_BATCH + sub * CHUNKS_PER_GROUP + ch;
            const float f = __expf(g_m_partial[pb] - M) * invL;
            float4 v = g_ctx_partial[(size_t)pb * (H / 4) + t];
            c.x = fmaf(f, v.x, c.x);
            c.y = fmaf(f, v.y, c.y);
            c.z = fmaf(f, v.z, c.z);
            c.w = fmaf(f, v.w, c.w);
        }
        g_ctx2[(size_t)g * (H / 4) + t] = c;
    }
}

// ---------------------------------------------------------------------------
// Kernel 2c: level-2 combine (8 groups -> context vector), 32 blocks.
// ---------------------------------------------------------------------------
__global__ __launch_bounds__(K2_THREADS)
void k2c_combine2(float* __restrict__ out_ctx)
{
    const int b = blockIdx.x;
    const int t = threadIdx.x;
    float4 c = make_float4(0.f, 0.f, 0.f, 0.f);
#pragma unroll
    for (int g = 0; g < GROUPS_PER_BATCH; ++g) {
        float4 v = g_ctx2[(size_t)(b * GROUPS_PER_BATCH + g) * (H / 4) + t];
        c.x += v.x; c.y += v.y; c.z += v.z; c.w += v.w;
    }
    reinterpret_cast<float4*>(out_ctx + (size_t)b * H)[t] = c;
}

extern "C" void kernel_launch(void* const* d_in, const int* in_sizes, int n_in,
                              void* d_out, int out_size)
{
    const float* query = (const float*)d_in[0];   // (32,1,1024)
    const float* keys  = (const float*)d_in[1];   // (32,4096,1024)
    float* out = (float*)d_out;
    float* out_ctx = out;                  // (B,H)
    float* out_w   = out + (size_t)B * H;  // (B,S)

    k1_scores_partial_ctx<<<K1_BLOCKS, K1_THREADS>>>(query, keys, out_w);
    k2a_stats<<<B, K2_THREADS>>>(out_w);
    k2b_norm_and_combine1<<<WNORM_BLOCKS + NGROUPS, K2_THREADS>>>(out_w);
    k2c_combine2<<<B, K2_THREADS>>>(out_ctx);
}

// round 4
// speedup vs baseline: 1.0902x; 1.0902x over previous
#include <cuda_runtime.h>
#include <math.h>

#define B 32
#define S 4096
#define H 1024
#define ROWS_PER_WARP 64
#define CHUNKS_PER_BATCH (S / ROWS_PER_WARP)          // 64
#define TOTAL_CHUNKS (B * CHUNKS_PER_BATCH)           // 2048
#define WARPS_PER_BLOCK 8
#define K1_THREADS (WARPS_PER_BLOCK * 32)             // 256
#define K1_BLOCKS (TOTAL_CHUNKS / WARPS_PER_BLOCK)    // 256

// level-1 combine grouping in finalize
#define CHUNKS_PER_GROUP 8
#define GROUPS_PER_BATCH (CHUNKS_PER_BATCH / CHUNKS_PER_GROUP)  // 8
#define NGROUPS (B * GROUPS_PER_BATCH)                          // 256

// Scratch (__device__ globals; no dynamic allocation allowed)
__device__ float4 g_ctx_partial[TOTAL_CHUNKS * (H / 4)];  // 8 MB
__device__ float  g_m_partial[TOTAL_CHUNKS];
__device__ float  g_l_partial[TOTAL_CHUNKS];
__device__ float  g_M[B];
__device__ float  g_invL[B];

// ---------------------------------------------------------------------------
// Kernel 1: single streaming pass over keys.
// One warp = one 64-row chunk. Per row: float4-coalesced load (__ldcs),
// q.k dot via warp shuffle reduce, raw score -> weights slot of d_out,
// online-softmax accumulation of partial context (8 x float4 regs) plus
// running (m, l).
// ---------------------------------------------------------------------------
__global__ __launch_bounds__(K1_THREADS)
void k1_scores_partial_ctx(const float* __restrict__ query,
                           const float* __restrict__ keys,
                           float* __restrict__ out_weights /* raw scores */)
{
    const int warp_global = blockIdx.x * WARPS_PER_BLOCK + (threadIdx.x >> 5);
    const int lane = threadIdx.x & 31;
    const int b     = warp_global / CHUNKS_PER_BATCH;
    const int chunk = warp_global % CHUNKS_PER_BATCH;
    const int s0    = chunk * ROWS_PER_WARP;

    const float4* q4 = reinterpret_cast<const float4*>(query + (size_t)b * H);
    float4 qv[8];
#pragma unroll
    for (int j = 0; j < 8; ++j) qv[j] = q4[lane + 32 * j];

    float4 acc[8];
#pragma unroll
    for (int j = 0; j < 8; ++j) acc[j] = make_float4(0.f, 0.f, 0.f, 0.f);
    float m = -INFINITY;
    float l = 0.f;

    const size_t base = ((size_t)b * S + s0) * H;

    for (int r = 0; r < ROWS_PER_WARP; ++r) {
        const float4* k4 = reinterpret_cast<const float4*>(keys + base + (size_t)r * H);
        float4 kv[8];
#pragma unroll
        for (int j = 0; j < 8; ++j) kv[j] = __ldcs(&k4[lane + 32 * j]);

        float d = 0.f;
#pragma unroll
        for (int j = 0; j < 8; ++j) {
            d = fmaf(qv[j].x, kv[j].x, d);
            d = fmaf(qv[j].y, kv[j].y, d);
            d = fmaf(qv[j].z, kv[j].z, d);
            d = fmaf(qv[j].w, kv[j].w, d);
        }
#pragma unroll
        for (int o = 16; o > 0; o >>= 1)
            d += __shfl_xor_sync(0xFFFFFFFFu, d, o);

        if (lane == 0) out_weights[(size_t)b * S + s0 + r] = d;

        float p;
        if (d > m) {
            float scale = __expf(m - d);   // first iter: exp(-inf)=0
#pragma unroll
            for (int j = 0; j < 8; ++j) {
                acc[j].x *= scale; acc[j].y *= scale;
                acc[j].z *= scale; acc[j].w *= scale;
            }
            l = fmaf(l, scale, 1.f);
            m = d;
            p = 1.f;
        } else {
            p = __expf(d - m);
            l += p;
        }
#pragma unroll
        for (int j = 0; j < 8; ++j) {
            acc[j].x = fmaf(p, kv[j].x, acc[j].x);
            acc[j].y = fmaf(p, kv[j].y, acc[j].y);
            acc[j].z = fmaf(p, kv[j].z, acc[j].z);
            acc[j].w = fmaf(p, kv[j].w, acc[j].w);
        }
    }

    float4* dst = &g_ctx_partial[(size_t)warp_global * (H / 4)];
#pragma unroll
    for (int j = 0; j < 8; ++j) dst[lane + 32 * j] = acc[j];
    if (lane == 0) {
        g_m_partial[warp_global] = m;
        g_l_partial[warp_global] = l;
    }
}

// ---------------------------------------------------------------------------
// Kernel 2a: one block per batch (64 threads).
// M_b = max_c m_c ;  L_b = sum_c l_c * exp(m_c - M_b). Also zeroes out_ctx[b].
// ---------------------------------------------------------------------------
__global__ __launch_bounds__(64)
void k2a_stats(float* __restrict__ out_ctx)
{
    const int b = blockIdx.x;
    const int t = threadIdx.x;           // 0..63, one chunk each
    __shared__ float sm[2], sl[2], sM;

    const int c = b * CHUNKS_PER_BATCH + t;
    const float mc = g_m_partial[c];
    const float lc = g_l_partial[c];

    // zero the context output (poisoned by harness)
    float4* oc = reinterpret_cast<float4*>(out_ctx + (size_t)b * H);
#pragma unroll
    for (int j = 0; j < 4; ++j)
        oc[t + 64 * j] = make_float4(0.f, 0.f, 0.f, 0.f);

    // max over 64
    float v = mc;
#pragma unroll
    for (int o = 16; o > 0; o >>= 1)
        v = fmaxf(v, __shfl_xor_sync(0xFFFFFFFFu, v, o));
    if ((t & 31) == 0) sm[t >> 5] = v;
    __syncthreads();
    if (t == 0) sM = fmaxf(sm[0], sm[1]);
    __syncthreads();
    const float M = sM;

    // sum l_c * exp(m_c - M)
    float s = lc * __expf(mc - M);
#pragma unroll
    for (int o = 16; o > 0; o >>= 1)
        s += __shfl_xor_sync(0xFFFFFFFFu, s, o);
    if ((t & 31) == 0) sl[t >> 5] = s;
    __syncthreads();
    if (t == 0) {
        g_M[b] = M;
        g_invL[b] = 1.f / (sl[0] + sl[1]);
    }
}

// ---------------------------------------------------------------------------
// Kernel 2b: blocks 0..127 normalize weights (float4);
// blocks 128..383: combine 8 chunk-partials each, atomicAdd into out_ctx.
// ---------------------------------------------------------------------------
#define K2_THREADS 256
#define WNORM_BLOCKS ((B * S / 4) / K2_THREADS)   // 128

__global__ __launch_bounds__(K2_THREADS)
void k2b_finalize(float* __restrict__ out_ctx, float* __restrict__ out_weights)
{
    if (blockIdx.x < WNORM_BLOCKS) {
        const int idx = blockIdx.x * K2_THREADS + threadIdx.x;  // float4 idx
        const int b = idx / (S / 4);
        const float M = g_M[b], invL = g_invL[b];
        float4 s = reinterpret_cast<float4*>(out_weights)[idx];
        s.x = __expf(s.x - M) * invL;
        s.y = __expf(s.y - M) * invL;
        s.z = __expf(s.z - M) * invL;
        s.w = __expf(s.w - M) * invL;
        reinterpret_cast<float4*>(out_weights)[idx] = s;
    } else {
        const int g   = blockIdx.x - WNORM_BLOCKS;   // 0..255
        const int b   = g / GROUPS_PER_BATCH;
        const int sub = g % GROUPS_PER_BATCH;
        const float M = g_M[b], invL = g_invL[b];
        const int t = threadIdx.x;                   // float4 element t of 256
        float4 c = make_float4(0.f, 0.f, 0.f, 0.f);
#pragma unroll
        for (int ch = 0; ch < CHUNKS_PER_GROUP; ++ch) {
            const int pb = b * CHUNKS_PER_BATCH + sub * CHUNKS_PER_GROUP + ch;
            const float f = __expf(g_m_partial[pb] - M) * invL;
            float4 v = g_ctx_partial[(size_t)pb * (H / 4) + t];
            c.x = fmaf(f, v.x, c.x);
            c.y = fmaf(f, v.y, c.y);
            c.z = fmaf(f, v.z, c.z);
            c.w = fmaf(f, v.w, c.w);
        }
        float* o = out_ctx + (size_t)b * H + 4 * t;
        atomicAdd(o + 0, c.x);
        atomicAdd(o + 1, c.y);
        atomicAdd(o + 2, c.z);
        atomicAdd(o + 3, c.w);
    }
}

extern "C" void kernel_launch(void* const* d_in, const int* in_sizes, int n_in,
                              void* d_out, int out_size)
{
    const float* query = (const float*)d_in[0];   // (32,1,1024)
    const float* keys  = (const float*)d_in[1];   // (32,4096,1024)
    float* out = (float*)d_out;
    float* out_ctx = out;                  // (B,H)
    float* out_w   = out + (size_t)B * H;  // (B,S)

    k1_scores_partial_ctx<<<K1_BLOCKS, K1_THREADS>>>(query, keys, out_w);
    k2a_stats<<<B, 64>>>(out_ctx);
    k2b_finalize<<<WNORM_BLOCKS + NGROUPS, K2_THREADS>>>(out_ctx, out_w);
}